// round 16
// baseline (speedup 1.0000x reference)
#include <cuda_runtime.h>
#include <cstdint>

#define NB      160            // 5*32 boxes per batch
#define NT      256
#define RSPLIT  8
#define ROWS    64             // rows per CTA
#define MW      17             // padded mask row stride (words) -> conflict-free
#define NCTAS   (64 * RSPLIT)

__device__ float    g_part[64][RSPLIT][4];  // [tanh_sum, painted_tanh_sum, count]
__device__ unsigned g_count = 0;            // self-resetting last-CTA counter

// hardware tanh: 1 MUFU op
__device__ __forceinline__ float htanh(float x) {
    float t;
    asm("tanh.approx.f32 %0, %1;" : "=f"(t) : "f"(x));
    return t;
}

__global__ void __launch_bounds__(NT, 4)
mml_fused(const float* __restrict__ pred, const int* __restrict__ tgt,
          float* __restrict__ out)
{
    const int b    = blockIdx.x;
    const int seg  = blockIdx.y;
    const int row0 = seg * ROWS;
    const int tid  = threadIdx.x;
    const int lane = tid & 31;
    const int warp = tid >> 5;

    __shared__ int4     cbox[NB];          // compacted: (r0loc, r1loc, y1, y2)
    __shared__ int      s_nbox;
    __shared__ unsigned sm[ROWS * MW];     // padded mask tile (64 rows)
    __shared__ float    red[3][NT / 32];
    __shared__ float    shl[64];
    __shared__ bool     isLast;

    // box load overlaps smem zeroing
    const int4* tb = (const int4*)(tgt + (size_t)b * NB * 4);
    int4 mybox;
    if (tid < NB) mybox = tb[tid];

    if (tid == 0) s_nbox = 0;
    for (int i = tid; i < ROWS * MW; i += NT) sm[i] = 0u;
    __syncthreads();

    // ---- compact boxes intersecting this 64-row segment ----
    if (tid < NB) {
        int x1 = min(mybox.x, 512),           y1 = min(mybox.y, 512);
        int x2 = min(mybox.x + mybox.z, 512), y2 = min(mybox.y + mybox.w, 512);
        if (x2 > row0 && x1 < row0 + ROWS && y2 > y1) {
            int slot = atomicAdd(&s_nbox, 1);
            cbox[slot] = make_int4(max(x1 - row0, 0), min(x2 - row0, ROWS), y1, y2);
        }
    }
    __syncthreads();
    const int nbox = s_nbox;

    // ---- warp-per-box paint: lanes stride rows; padded stride -> conflict-free ----
    for (int i = warp; i < nbox; i += NT / 32) {
        int4 bx = cbox[i];
        int wlo = bx.z >> 5, whi = (bx.w - 1) >> 5;
        unsigned loMask = ~((1u << (bx.z & 31)) - 1u);
        unsigned hiMask = 0xFFFFFFFFu >> (31 - ((bx.w - 1) & 31));
        for (int r = bx.x + lane; r < bx.y; r += 32) {
            unsigned* mrow = &sm[r * MW];
            for (int w = wlo; w <= whi; w++) {
                unsigned bits = 0xFFFFFFFFu;
                if (w == wlo) bits &= loMask;
                if (w == whi) bits &= hiMask;
                atomicOr(&mrow[w], bits);
            }
        }
    }
    __syncthreads();

    // ---- exact painted count: thread owns 4 cells (tid + 256j) ----
    float cntf = 0.f;
    #pragma unroll
    for (int j = 0; j < 4; j++) {
        int c = tid + NT * j;
        cntf += (float)__popc(sm[(c >> 4) * MW + (c & 15)]);
    }

    // ---- prepack this thread's 32 mask nibbles into 4 u32 regs ----
    const int c4   = tid & 127;
    const int wofs = c4 >> 3;
    const int msh  = (c4 & 7) * 4;
    const int rb   = tid >> 7;                 // 0 or 1; rows rb + 2k
    unsigned mreg[4];
    #pragma unroll
    for (int g = 0; g < 4; g++) {
        unsigned m = 0u;
        #pragma unroll
        for (int j = 0; j < 8; j++) {
            int k = g * 8 + j;
            m |= ((sm[(rb + 2 * k) * MW + wofs] >> msh) & 0xFu) << (4 * j);
        }
        mreg[g] = m;
    }

    // ---- streaming: 4 groups of 8 front-batched LDG.128 (MLP_p1 = 8) ----
    float tsum = 0.f, tisum = 0.f;
    const float4* p = (const float4*)(pred + ((size_t)b * 512 + row0) * 512);

#define PROC(v, mw)                                                        \
    {   float t0 = htanh(0.5f * (v).x), t1 = htanh(0.5f * (v).y);          \
        float t2 = htanh(0.5f * (v).z), t3 = htanh(0.5f * (v).w);          \
        tsum += (t0 + t1) + (t2 + t3);                                     \
        float a0 = ((mw) & 1u) ? t0 : 0.f;                                 \
        float a1 = ((mw) & 2u) ? t1 : 0.f;                                 \
        float a2 = ((mw) & 4u) ? t2 : 0.f;                                 \
        float a3 = ((mw) & 8u) ? t3 : 0.f;                                 \
        tisum += (a0 + a1) + (a2 + a3); }

    #pragma unroll
    for (int g = 0; g < 4; g++) {
        // 8 consecutive LDG.128 with no intervening math -> batched in SASS
        const float4* base = p + tid + NT * 8 * g;
        float4 v0 = base[0];
        float4 v1 = base[NT];
        float4 v2 = base[2 * NT];
        float4 v3 = base[3 * NT];
        float4 v4 = base[4 * NT];
        float4 v5 = base[5 * NT];
        float4 v6 = base[6 * NT];
        float4 v7 = base[7 * NT];
        const unsigned nib = mreg[g];
        PROC(v0, (nib      ) & 0xFu);
        PROC(v1, (nib >>  4) & 0xFu);
        PROC(v2, (nib >>  8) & 0xFu);
        PROC(v3, (nib >> 12) & 0xFu);
        PROC(v4, (nib >> 16) & 0xFu);
        PROC(v5, (nib >> 20) & 0xFu);
        PROC(v6, (nib >> 24) & 0xFu);
        PROC(v7, (nib >> 28) & 0xFu);
    }
#undef PROC

    // ---- block reduce ----
    #pragma unroll
    for (int off = 16; off; off >>= 1) {
        tsum  += __shfl_down_sync(0xffffffffu, tsum,  off);
        tisum += __shfl_down_sync(0xffffffffu, tisum, off);
        cntf  += __shfl_down_sync(0xffffffffu, cntf,  off);
    }
    if (lane == 0) { red[0][warp] = tsum; red[1][warp] = tisum; red[2][warp] = cntf; }
    __syncthreads();
    if (tid == 0) {
        float T = 0.f, TI = 0.f, C = 0.f;
        #pragma unroll
        for (int w = 0; w < NT / 32; w++) { T += red[0][w]; TI += red[1][w]; C += red[2][w]; }
        g_part[b][seg][0] = T;
        g_part[b][seg][1] = TI;
        g_part[b][seg][2] = C;
        __threadfence();
        unsigned prev = atomicAdd(&g_count, 1u);
        isLast = (prev == NCTAS - 1);
        if (isLast) g_count = 0;               // self-reset for graph replay
    }
    __syncthreads();

    // ---- fused final dice reduction in last CTA ----
    if (isLast) {
        __threadfence();
        if (tid < 64) {
            volatile float* gp = (volatile float*)g_part;
            float T = 0.f, TI = 0.f, C = 0.f;
            for (int s = 0; s < RSPLIT; s++) {
                T  += gp[(tid * RSPLIT + s) * 4 + 0];
                TI += gp[(tid * RSPLIT + s) * 4 + 1];
                C  += gp[(tid * RSPLIT + s) * 4 + 2];
            }
            // unfold: P = 0.5*T + 0.5*512*512 ; I = 0.5*TI + 0.5*C
            float P = 0.5f * T + 131072.0f;
            float I = 0.5f * TI + 0.5f * C;
            float inter = 255.f * I;
            shl[tid] = (inter + 1.f) / (P + 255.f * C - inter + 1.f);
        }
        __syncthreads();
        #pragma unroll
        for (int off = 32; off; off >>= 1) {
            if (tid < off && tid + off < 64) shl[tid] += shl[tid + off];
            __syncthreads();
        }
        if (tid == 0) out[0] = 1.0f - shl[0] * (1.0f / 64.0f);
    }
}

extern "C" void kernel_launch(void* const* d_in, const int* in_sizes, int n_in,
                              void* d_out, int out_size) {
    const float* pred = (const float*)d_in[0];   // (64,1,512,512) fp32
    const int*   tgt  = (const int*)d_in[1];     // (64,5,32,4) int32
    float* out = (float*)d_out;                  // scalar

    mml_fused<<<dim3(64, RSPLIT), NT>>>(pred, tgt, out);
}